// round 7
// baseline (speedup 1.0000x reference)
#include <cuda_runtime.h>
#include <math.h>

static constexpr int H  = 512;
static constexpr int G4 = 2048;
static constexpr int B  = 128;
static constexpr int T  = 256;
static constexpr int V  = 128;
static constexpr int LW = 32;
static constexpr int NL = 2;
static constexpr int BH = B * H;
static constexpr int E2 = 2 * H;

static constexpr long OUT_HF  = (long)B * LW * V;
static constexpr long OUT_CF  = OUT_HF + (long)NL * BH;
static constexpr long OUT_ATT = OUT_CF + (long)NL * BH;

// ---- scratch (device globals; no runtime allocation) ----
__device__ float g_l0[(size_t)T * B * E2];   // layer0 out [t][b][2H]
__device__ float g_enc[(size_t)B * T * E2];  // encoder out [b][t][2H]
__device__ float g_eh[2 * 2 * BH];           // enc h [phase][dir][B][H]
__device__ float g_ec[2 * BH];               // enc c [dir][B][H]
__device__ float g_dh[2 * 2 * BH];           // dec h [phase][layer][B][H]
__device__ float g_dc[2 * BH];               // dec c [layer][B][H]
__device__ float g_din[BH];
__device__ float g_q[B * E2];
__device__ float g_cx[B * E2];
__device__ float g_cb[BH];
__device__ int   g_tok[B];

__device__ __forceinline__ float sigf(float x) { return 1.0f / (1.0f + expf(-x)); }

// ---- 32x64 tile GEMM accumulate, 128 threads, 4x4 per thread ----
__device__ __forceinline__ void tile_acc(float acc[4][4],
    const float* __restrict__ A, int lda, int K,
    const float* __restrict__ W, int ldw, int wcol,
    float* a_sm, float* w_sm, int tid, int rg4, int cg4)
{
    const int ar = tid >> 2;
    const int ak = (tid & 3) << 2;
    const int wk = tid >> 4;
    for (int kt = 0; kt < K; kt += 16) {
        __syncthreads();
        float4 av = *(const float4*)(A + (size_t)ar * lda + kt + ak);
        a_sm[(ak + 0) * 32 + ar] = av.x;
        a_sm[(ak + 1) * 32 + ar] = av.y;
        a_sm[(ak + 2) * 32 + ar] = av.z;
        a_sm[(ak + 3) * 32 + ar] = av.w;
        *(float4*)(w_sm + wk * 64 + cg4) =
            *(const float4*)(W + (size_t)(kt + wk) * ldw + wcol);
        *(float4*)(w_sm + (wk + 8) * 64 + cg4) =
            *(const float4*)(W + (size_t)(kt + wk + 8) * ldw + wcol);
        __syncthreads();
#pragma unroll
        for (int k = 0; k < 16; ++k) {
            float4 a4 = *(const float4*)(a_sm + k * 32 + rg4);
            float4 w4 = *(const float4*)(w_sm + k * 64 + cg4);
            acc[0][0] = fmaf(a4.x, w4.x, acc[0][0]);
            acc[0][1] = fmaf(a4.x, w4.y, acc[0][1]);
            acc[0][2] = fmaf(a4.x, w4.z, acc[0][2]);
            acc[0][3] = fmaf(a4.x, w4.w, acc[0][3]);
            acc[1][0] = fmaf(a4.y, w4.x, acc[1][0]);
            acc[1][1] = fmaf(a4.y, w4.y, acc[1][1]);
            acc[1][2] = fmaf(a4.y, w4.z, acc[1][2]);
            acc[1][3] = fmaf(a4.y, w4.w, acc[1][3]);
            acc[2][0] = fmaf(a4.z, w4.x, acc[2][0]);
            acc[2][1] = fmaf(a4.z, w4.y, acc[2][1]);
            acc[2][2] = fmaf(a4.z, w4.z, acc[2][2]);
            acc[2][3] = fmaf(a4.z, w4.w, acc[2][3]);
            acc[3][0] = fmaf(a4.w, w4.x, acc[3][0]);
            acc[3][1] = fmaf(a4.w, w4.y, acc[3][1]);
            acc[3][2] = fmaf(a4.w, w4.z, acc[3][2]);
            acc[3][3] = fmaf(a4.w, w4.w, acc[3][3]);
        }
    }
}

__device__ __forceinline__ void store_gates(float acc[4][4], float* gs, int rg4, int cg4)
{
#pragma unroll
    for (int i = 0; i < 4; ++i)
#pragma unroll
        for (int j = 0; j < 4; ++j)
            gs[(rg4 + i) * 64 + cg4 + j] = acc[i][j];
}

// gate_sm local cols: [0:16)=i [16:32)=f [32:48)=g [48:64)=o for 16 units
__device__ __forceinline__ void cell_update(const float* gs, int tid, int b0, int u0,
    float* __restrict__ cd, float* __restrict__ hd,
    float* __restrict__ seqbase, size_t sbstride)
{
#pragma unroll
    for (int q = 0; q < 4; ++q) {
        int flat = tid * 4 + q;
        int r = flat >> 4, u = flat & 15;
        int b = b0 + r, uu = u0 + u;
        float iv = gs[r * 64 + u];
        float fv = gs[r * 64 + 16 + u];
        float gv = gs[r * 64 + 32 + u];
        float ov = gs[r * 64 + 48 + u];
        float cn = sigf(fv) * cd[b * H + uu] + sigf(iv) * tanhf(gv);
        float hn = sigf(ov) * tanhf(cn);
        cd[b * H + uu] = cn;
        hd[b * H + uu] = hn;
        if (seqbase) seqbase[(size_t)b * sbstride + uu] = hn;
    }
}

__global__ void __launch_bounds__(128) enc0_step(
    const float* __restrict__ x, const float* __restrict__ Wih,
    const float* __restrict__ Whh, const float* __restrict__ bias, int s)
{
    __shared__ float a_sm[16 * 32], w_sm[16 * 64], gate_sm[32 * 64];
    int tid = threadIdx.x, dir = blockIdx.z;
    int t = dir ? (T - 1 - s) : s;
    int u0 = blockIdx.x * 16, b0 = blockIdx.y * 32;
    int cg4 = (tid & 15) * 4, rg4 = (tid >> 4) * 4;
    int wcol = (cg4 >> 4) * H + u0 + (cg4 & 15);

    const float* Wd  = Wih + dir * 2 * G4;
    const float* Whd = Whh + (size_t)dir * H * G4;
    const float* bd  = bias + dir * G4;
    float* hin  = g_eh + (s & 1) * 2 * BH + dir * BH;
    float* hout = g_eh + ((s + 1) & 1) * 2 * BH + dir * BH;
    float* cd   = g_ec + dir * BH;

    float4 bw  = *(const float4*)(bd + wcol);
    float4 wi0 = *(const float4*)(Wd + wcol);
    float4 wi1 = *(const float4*)(Wd + G4 + wcol);
    float acc[4][4];
#pragma unroll
    for (int i = 0; i < 4; ++i) {
        int b = b0 + rg4 + i;
        float x0 = x[(size_t)b * T * 2 + t * 2 + 0];
        float x1 = x[(size_t)b * T * 2 + t * 2 + 1];
        acc[i][0] = bw.x + x0 * wi0.x + x1 * wi1.x;
        acc[i][1] = bw.y + x0 * wi0.y + x1 * wi1.y;
        acc[i][2] = bw.z + x0 * wi0.z + x1 * wi1.z;
        acc[i][3] = bw.w + x0 * wi0.w + x1 * wi1.w;
    }
    tile_acc(acc, hin + (size_t)b0 * H, H, H, Whd, G4, wcol, a_sm, w_sm, tid, rg4, cg4);
    __syncthreads();
    store_gates(acc, gate_sm, rg4, cg4);
    __syncthreads();
    cell_update(gate_sm, tid, b0, u0, cd, hout,
                g_l0 + (size_t)t * B * E2 + dir * H, E2);
}

__global__ void __launch_bounds__(128) enc1_step(
    const float* __restrict__ Wih, const float* __restrict__ Whh,
    const float* __restrict__ bias, int s)
{
    __shared__ float a_sm[16 * 32], w_sm[16 * 64], gate_sm[32 * 64];
    int tid = threadIdx.x, dir = blockIdx.z;
    int t = dir ? (T - 1 - s) : s;
    int u0 = blockIdx.x * 16, b0 = blockIdx.y * 32;
    int cg4 = (tid & 15) * 4, rg4 = (tid >> 4) * 4;
    int wcol = (cg4 >> 4) * H + u0 + (cg4 & 15);

    const float* Wd  = Wih + (size_t)dir * E2 * G4;
    const float* Whd = Whh + (size_t)dir * H * G4;
    const float* bd  = bias + dir * G4;
    float* hin  = g_eh + (s & 1) * 2 * BH + dir * BH;
    float* hout = g_eh + ((s + 1) & 1) * 2 * BH + dir * BH;
    float* cd   = g_ec + dir * BH;

    float4 bw = *(const float4*)(bd + wcol);
    float acc[4][4];
#pragma unroll
    for (int i = 0; i < 4; ++i) {
        acc[i][0] = bw.x; acc[i][1] = bw.y; acc[i][2] = bw.z; acc[i][3] = bw.w;
    }
    tile_acc(acc, g_l0 + (size_t)t * B * E2 + (size_t)b0 * E2, E2, E2, Wd, G4, wcol,
             a_sm, w_sm, tid, rg4, cg4);
    tile_acc(acc, hin + (size_t)b0 * H, H, H, Whd, G4, wcol, a_sm, w_sm, tid, rg4, cg4);
    __syncthreads();
    store_gates(acc, gate_sm, rg4, cg4);
    __syncthreads();
    cell_update(gate_sm, tid, b0, u0, cd, hout,
                g_enc + (size_t)t * E2 + dir * H, (size_t)T * E2);
}

__global__ void __launch_bounds__(128) dec_step(
    const float* __restrict__ Wih, const float* __restrict__ Whh,
    const float* __restrict__ bias, int layer, int s)
{
    __shared__ float a_sm[16 * 32], w_sm[16 * 64], gate_sm[32 * 64];
    int tid = threadIdx.x;
    int u0 = blockIdx.x * 16, b0 = blockIdx.y * 32;
    int cg4 = (tid & 15) * 4, rg4 = (tid >> 4) * 4;
    int wcol = (cg4 >> 4) * H + u0 + (cg4 & 15);

    const float* Wd  = Wih + (size_t)layer * H * G4;
    const float* Whd = Whh + (size_t)layer * H * G4;
    const float* bd  = bias + layer * G4;
    const float* A1  = (layer == 0) ? g_din : (g_dh + ((s + 1) & 1) * 2 * BH);
    float* hin  = g_dh + (s & 1) * 2 * BH + layer * BH;
    float* hout = g_dh + ((s + 1) & 1) * 2 * BH + layer * BH;
    float* cd   = g_dc + layer * BH;

    float4 bw = *(const float4*)(bd + wcol);
    float acc[4][4];
#pragma unroll
    for (int i = 0; i < 4; ++i) {
        acc[i][0] = bw.x; acc[i][1] = bw.y; acc[i][2] = bw.z; acc[i][3] = bw.w;
    }
    tile_acc(acc, A1 + (size_t)b0 * H, H, H, Wd, G4, wcol, a_sm, w_sm, tid, rg4, cg4);
    tile_acc(acc, hin + (size_t)b0 * H, H, H, Whd, G4, wcol, a_sm, w_sm, tid, rg4, cg4);
    __syncthreads();
    store_gates(acc, gate_sm, rg4, cg4);
    __syncthreads();
    cell_update(gate_sm, tid, b0, u0, cd, hout, nullptr, 0);
}

__device__ __forceinline__ void gemm_core(
    const float* A1, int lda1, int K1, const float* W1,
    const float* A2, int lda2, int K2, const float* W2,
    int ldw, const float* bias, float* C, int ldc,
    float* a_sm, float* w_sm)
{
    int tid = threadIdx.x;
    int n0 = blockIdx.x * 64, b0 = blockIdx.y * 32;
    int cg4 = (tid & 15) * 4, rg4 = (tid >> 4) * 4;
    int wcol = n0 + cg4;
    float4 bw = *(const float4*)(bias + wcol);
    float acc[4][4];
#pragma unroll
    for (int i = 0; i < 4; ++i) {
        acc[i][0] = bw.x; acc[i][1] = bw.y; acc[i][2] = bw.z; acc[i][3] = bw.w;
    }
    tile_acc(acc, A1 + (size_t)b0 * lda1, lda1, K1, W1, ldw, wcol, a_sm, w_sm, tid, rg4, cg4);
    if (K2 > 0)
        tile_acc(acc, A2 + (size_t)b0 * lda2, lda2, K2, W2, ldw, wcol, a_sm, w_sm, tid, rg4, cg4);
#pragma unroll
    for (int i = 0; i < 4; ++i)
        *(float4*)(C + (size_t)(b0 + rg4 + i) * ldc + wcol) =
            make_float4(acc[i][0], acc[i][1], acc[i][2], acc[i][3]);
}

__global__ void __launch_bounds__(128) query_kernel(const float* __restrict__ Wq,
                                                    const float* __restrict__ bq, int s)
{
    __shared__ float a_sm[16 * 32], w_sm[16 * 64];
    const float* h1 = g_dh + ((s + 1) & 1) * 2 * BH + BH;
    gemm_core(h1, H, H, Wq, nullptr, 0, 0, nullptr, E2, bq, g_q, E2, a_sm, w_sm);
}

__global__ void __launch_bounds__(128) comb_kernel(const float* __restrict__ Wc,
                                                   const float* __restrict__ bc, int s)
{
    __shared__ float a_sm[16 * 32], w_sm[16 * 64];
    const float* h1 = g_dh + ((s + 1) & 1) * 2 * BH + BH;
    gemm_core(h1, H, H, Wc, g_cx, E2, E2, Wc + (size_t)H * H, H, bc, g_cb, H, a_sm, w_sm);
}

__global__ void __launch_bounds__(128) logits_kernel(const float* __restrict__ Wf,
                                                     const float* __restrict__ bf,
                                                     float* __restrict__ out, int s)
{
    __shared__ float a_sm[16 * 32], w_sm[16 * 64];
    gemm_core(g_cb, H, H, Wf, nullptr, 0, 0, nullptr, V, bf,
              out + (size_t)s * V, LW * V, a_sm, w_sm);
}

__global__ void __launch_bounds__(256) attn_kernel(float* __restrict__ out, int step)
{
    __shared__ float qs[E2];
    __shared__ float sc[T];
    __shared__ float red[8];
    int b = blockIdx.x, tid = threadIdx.x;
    const float* eb = g_enc + (size_t)b * T * E2;
    for (int j = tid; j < E2; j += 256) qs[j] = g_q[b * E2 + j];
    __syncthreads();
    int warp = tid >> 5, lane = tid & 31;
    for (int t = warp; t < T; t += 8) {
        const float* er = eb + (size_t)t * E2;
        float acc = 0.f;
#pragma unroll 8
        for (int j = lane; j < E2; j += 32) acc += er[j] * qs[j];
#pragma unroll
        for (int o = 16; o; o >>= 1) acc += __shfl_xor_sync(0xffffffffu, acc, o);
        if (lane == 0) sc[t] = acc;
    }
    __syncthreads();
    float v = sc[tid];
    float m = v;
#pragma unroll
    for (int o = 16; o; o >>= 1) m = fmaxf(m, __shfl_xor_sync(0xffffffffu, m, o));
    if (lane == 0) red[warp] = m;
    __syncthreads();
    float bm = red[0];
#pragma unroll
    for (int w = 1; w < 8; ++w) bm = fmaxf(bm, red[w]);
    float e = expf(v - bm);
    float ssum = e;
#pragma unroll
    for (int o = 16; o; o >>= 1) ssum += __shfl_xor_sync(0xffffffffu, ssum, o);
    __syncthreads();
    if (lane == 0) red[warp] = ssum;
    __syncthreads();
    float tot = 0.f;
#pragma unroll
    for (int w = 0; w < 8; ++w) tot += red[w];
    float p = e / tot;
    sc[tid] = p;
    out[OUT_ATT + (size_t)b * T * LW + (size_t)tid * LW + step] = p;
    __syncthreads();
    float a0 = 0.f, a1 = 0.f, a2 = 0.f, a3 = 0.f;
    for (int t = 0; t < T; ++t) {
        float pt = sc[t];
        const float* er = eb + (size_t)t * E2;
        a0 = fmaf(pt, er[tid], a0);
        a1 = fmaf(pt, er[tid + 256], a1);
        a2 = fmaf(pt, er[tid + 512], a2);
        a3 = fmaf(pt, er[tid + 768], a3);
    }
    g_cx[b * E2 + tid]       = a0;
    g_cx[b * E2 + tid + 256] = a1;
    g_cx[b * E2 + tid + 512] = a2;
    g_cx[b * E2 + tid + 768] = a3;
}

__global__ void argmax_kernel(const float* __restrict__ out, int step)
{
    int b = blockIdx.x, tid = threadIdx.x;   // 128 threads = V
    float v = out[(size_t)b * LW * V + (size_t)step * V + tid];
    int idx = tid;
#pragma unroll
    for (int o = 16; o; o >>= 1) {
        float ov = __shfl_xor_sync(0xffffffffu, v, o);
        int oi = __shfl_xor_sync(0xffffffffu, idx, o);
        if (ov > v || (ov == v && oi < idx)) { v = ov; idx = oi; }
    }
    __shared__ float sv[4];
    __shared__ int si[4];
    if ((tid & 31) == 0) { sv[tid >> 5] = v; si[tid >> 5] = idx; }
    __syncthreads();
    if (tid == 0) {
#pragma unroll
        for (int w = 1; w < 4; ++w)
            if (sv[w] > v || (sv[w] == v && si[w] < idx)) { v = sv[w]; idx = si[w]; }
        g_tok[b] = idx;
    }
}

__global__ void gather_emb(const float* __restrict__ emb)
{
    g_din[blockIdx.x * H + threadIdx.x] = emb[(size_t)g_tok[blockIdx.x] * H + threadIdx.x];
}

__global__ void init_tok() { g_tok[threadIdx.x] = 1; }   // SOS = 1

__global__ void zero_enc()
{
    int i = blockIdx.x * blockDim.x + threadIdx.x;
    if (i < 4 * BH) g_eh[i] = 0.f;
    if (i < 2 * BH) g_ec[i] = 0.f;
}

__global__ void sum_states(int l)
{
    int i = blockIdx.x * blockDim.x + threadIdx.x;
    if (i < BH) {
        g_dh[l * BH + i] = g_eh[i] + g_eh[BH + i];   // phase0 holds finals after T steps
        g_dc[l * BH + i] = g_ec[i] + g_ec[BH + i];
    }
}

__global__ void final_copy(float* __restrict__ out)
{
    int i = blockIdx.x * blockDim.x + threadIdx.x;
    if (i < NL * BH) {
        out[OUT_HF + i] = g_dh[i];   // phase 0 after 32 decoder steps
        out[OUT_CF + i] = g_dc[i];
    }
}

extern "C" void kernel_launch(void* const* d_in, const int* in_sizes, int n_in,
                              void* d_out, int out_size)
{
    const float* x     = (const float*)d_in[0];
    const float* e0Wih = (const float*)d_in[1];
    const float* e0Whh = (const float*)d_in[2];
    const float* e0b   = (const float*)d_in[3];
    const float* e1Wih = (const float*)d_in[4];
    const float* e1Whh = (const float*)d_in[5];
    const float* e1b   = (const float*)d_in[6];
    const float* dWih  = (const float*)d_in[7];
    const float* dWhh  = (const float*)d_in[8];
    const float* db    = (const float*)d_in[9];
    const float* emb   = (const float*)d_in[10];
    const float* Wq    = (const float*)d_in[11];
    const float* bq    = (const float*)d_in[12];
    const float* Wc    = (const float*)d_in[13];
    const float* bc    = (const float*)d_in[14];
    const float* Wf    = (const float*)d_in[15];
    const float* bf    = (const float*)d_in[16];
    float* out = (float*)d_out;

    dim3 gL(32, 4, 2), gD(32, 4, 1);

    zero_enc<<<(4 * BH + 255) / 256, 256>>>();
    for (int s = 0; s < T; ++s)
        enc0_step<<<gL, 128>>>(x, e0Wih, e0Whh, e0b, s);
    sum_states<<<256, 256>>>(0);

    zero_enc<<<(4 * BH + 255) / 256, 256>>>();
    for (int s = 0; s < T; ++s)
        enc1_step<<<gL, 128>>>(e1Wih, e1Whh, e1b, s);
    sum_states<<<256, 256>>>(1);

    init_tok<<<1, B>>>();
    for (int s = 0; s < LW; ++s) {
        gather_emb<<<B, H>>>(emb);
        dec_step<<<gD, 128>>>(dWih, dWhh, db, 0, s);
        dec_step<<<gD, 128>>>(dWih, dWhh, db, 1, s);
        query_kernel<<<dim3(16, 4), 128>>>(Wq, bq, s);
        attn_kernel<<<B, 256>>>(out, s);
        comb_kernel<<<dim3(8, 4), 128>>>(Wc, bc, s);
        logits_kernel<<<dim3(2, 4), 128>>>(Wf, bf, out, s);
        argmax_kernel<<<B, 128>>>(out, s);
    }
    final_copy<<<512, 256>>>(out);
}

// round 8
// speedup vs baseline: 1.1829x; 1.1829x over previous
#include <cuda_runtime.h>
#include <math.h>

static constexpr int H  = 512;
static constexpr int G4 = 2048;
static constexpr int B  = 128;
static constexpr int T  = 256;
static constexpr int V  = 128;
static constexpr int LW = 32;
static constexpr int NL = 2;
static constexpr int BH = B * H;
static constexpr int E2 = 2 * H;

static constexpr long OUT_HF  = (long)B * LW * V;
static constexpr long OUT_CF  = OUT_HF + (long)NL * BH;
static constexpr long OUT_ATT = OUT_CF + (long)NL * BH;

// ---- scratch (device globals; no runtime allocation) ----
__device__ float g_l0[(size_t)T * B * E2];   // layer0 out [t][b][2H]
__device__ float g_enc[(size_t)B * T * E2];  // encoder out [b][t][2H]
__device__ float g_eh[2 * 2 * BH];           // enc h [phase][dir][B][H]
__device__ float g_ec[2 * BH];               // enc c [dir][B][H]
__device__ float g_dh[2 * 2 * BH];           // dec h [phase][layer][B][H]
__device__ float g_dc[2 * BH];               // dec c [layer][B][H]
__device__ float g_din[BH];
__device__ float g_q[B * E2];
__device__ float g_cx[B * E2];
__device__ float g_cb[BH];
__device__ int   g_tok[B];

__device__ __forceinline__ float sigf(float x) { return 1.0f / (1.0f + expf(-x)); }

// ---- 32x64 tile GEMM accumulate, 128 threads, 4x4 per thread.
// Double-buffered smem, register prefetch, ONE __syncthreads per 16-k chunk.
// a_sm: 2*16*32 floats, w_sm: 2*16*64 floats.
__device__ __forceinline__ void tile_acc(float acc[4][4],
    const float* __restrict__ A, int lda, int K,
    const float* __restrict__ W, int ldw, int wcol,
    float* a_sm, float* w_sm, int tid, int rg4, int cg4)
{
    const int ar = tid >> 2;
    const int ak = (tid & 3) << 2;
    const int wk = tid >> 4;
    // preload chunk 0 into registers
    float4 av  = *(const float4*)(A + (size_t)ar * lda + ak);
    float4 wv0 = *(const float4*)(W + (size_t)wk * ldw + wcol);
    float4 wv1 = *(const float4*)(W + (size_t)(wk + 8) * ldw + wcol);
    __syncthreads();                       // protect buffer 0 from prior readers
    a_sm[(ak + 0) * 32 + ar] = av.x;
    a_sm[(ak + 1) * 32 + ar] = av.y;
    a_sm[(ak + 2) * 32 + ar] = av.z;
    a_sm[(ak + 3) * 32 + ar] = av.w;
    *(float4*)(w_sm + wk * 64 + cg4)       = wv0;
    *(float4*)(w_sm + (wk + 8) * 64 + cg4) = wv1;
    __syncthreads();
    int buf = 0;
    for (int kt = 0; kt < K; kt += 16) {
        const bool more = (kt + 16 < K);
        if (more) {                        // prefetch next chunk (hidden under compute)
            av  = *(const float4*)(A + (size_t)ar * lda + kt + 16 + ak);
            wv0 = *(const float4*)(W + (size_t)(kt + 16 + wk) * ldw + wcol);
            wv1 = *(const float4*)(W + (size_t)(kt + 24 + wk) * ldw + wcol);
        }
        const float* as = a_sm + buf * (16 * 32);
        const float* ws = w_sm + buf * (16 * 64);
#pragma unroll
        for (int k = 0; k < 16; ++k) {
            float4 a4 = *(const float4*)(as + k * 32 + rg4);
            float4 w4 = *(const float4*)(ws + k * 64 + cg4);
            acc[0][0] = fmaf(a4.x, w4.x, acc[0][0]);
            acc[0][1] = fmaf(a4.x, w4.y, acc[0][1]);
            acc[0][2] = fmaf(a4.x, w4.z, acc[0][2]);
            acc[0][3] = fmaf(a4.x, w4.w, acc[0][3]);
            acc[1][0] = fmaf(a4.y, w4.x, acc[1][0]);
            acc[1][1] = fmaf(a4.y, w4.y, acc[1][1]);
            acc[1][2] = fmaf(a4.y, w4.z, acc[1][2]);
            acc[1][3] = fmaf(a4.y, w4.w, acc[1][3]);
            acc[2][0] = fmaf(a4.z, w4.x, acc[2][0]);
            acc[2][1] = fmaf(a4.z, w4.y, acc[2][1]);
            acc[2][2] = fmaf(a4.z, w4.z, acc[2][2]);
            acc[2][3] = fmaf(a4.z, w4.w, acc[2][3]);
            acc[3][0] = fmaf(a4.w, w4.x, acc[3][0]);
            acc[3][1] = fmaf(a4.w, w4.y, acc[3][1]);
            acc[3][2] = fmaf(a4.w, w4.z, acc[3][2]);
            acc[3][3] = fmaf(a4.w, w4.w, acc[3][3]);
        }
        if (more) {
            buf ^= 1;
            float* asn = a_sm + buf * (16 * 32);
            float* wsn = w_sm + buf * (16 * 64);
            asn[(ak + 0) * 32 + ar] = av.x;
            asn[(ak + 1) * 32 + ar] = av.y;
            asn[(ak + 2) * 32 + ar] = av.z;
            asn[(ak + 3) * 32 + ar] = av.w;
            *(float4*)(wsn + wk * 64 + cg4)       = wv0;
            *(float4*)(wsn + (wk + 8) * 64 + cg4) = wv1;
            __syncthreads();
        }
    }
}

__device__ __forceinline__ void store_gates(float acc[4][4], float* gs, int rg4, int cg4)
{
#pragma unroll
    for (int i = 0; i < 4; ++i)
#pragma unroll
        for (int j = 0; j < 4; ++j)
            gs[(rg4 + i) * 64 + cg4 + j] = acc[i][j];
}

// gate_sm local cols: [0:16)=i [16:32)=f [32:48)=g [48:64)=o for 16 units
__device__ __forceinline__ void cell_update(const float* gs, int tid, int b0, int u0,
    float* __restrict__ cd, float* __restrict__ hd,
    float* __restrict__ seqbase, size_t sbstride)
{
#pragma unroll
    for (int q = 0; q < 4; ++q) {
        int flat = tid * 4 + q;
        int r = flat >> 4, u = flat & 15;
        int b = b0 + r, uu = u0 + u;
        float iv = gs[r * 64 + u];
        float fv = gs[r * 64 + 16 + u];
        float gv = gs[r * 64 + 32 + u];
        float ov = gs[r * 64 + 48 + u];
        float cn = sigf(fv) * cd[b * H + uu] + sigf(iv) * tanhf(gv);
        float hn = sigf(ov) * tanhf(cn);
        cd[b * H + uu] = cn;
        hd[b * H + uu] = hn;
        if (seqbase) seqbase[(size_t)b * sbstride + uu] = hn;
    }
}

__global__ void __launch_bounds__(128) enc0_step(
    const float* __restrict__ x, const float* __restrict__ Wih,
    const float* __restrict__ Whh, const float* __restrict__ bias, int s)
{
    __shared__ float a_sm[2 * 16 * 32], w_sm[2 * 16 * 64], gate_sm[32 * 64];
    int tid = threadIdx.x, dir = blockIdx.z;
    int t = dir ? (T - 1 - s) : s;
    int u0 = blockIdx.x * 16, b0 = blockIdx.y * 32;
    int cg4 = (tid & 15) * 4, rg4 = (tid >> 4) * 4;
    int wcol = (cg4 >> 4) * H + u0 + (cg4 & 15);

    const float* Wd  = Wih + dir * 2 * G4;
    const float* Whd = Whh + (size_t)dir * H * G4;
    const float* bd  = bias + dir * G4;
    float* hin  = g_eh + (s & 1) * 2 * BH + dir * BH;
    float* hout = g_eh + ((s + 1) & 1) * 2 * BH + dir * BH;
    float* cd   = g_ec + dir * BH;

    float4 bw  = *(const float4*)(bd + wcol);
    float4 wi0 = *(const float4*)(Wd + wcol);
    float4 wi1 = *(const float4*)(Wd + G4 + wcol);
    float acc[4][4];
#pragma unroll
    for (int i = 0; i < 4; ++i) {
        int b = b0 + rg4 + i;
        float x0 = x[(size_t)b * T * 2 + t * 2 + 0];
        float x1 = x[(size_t)b * T * 2 + t * 2 + 1];
        acc[i][0] = bw.x + x0 * wi0.x + x1 * wi1.x;
        acc[i][1] = bw.y + x0 * wi0.y + x1 * wi1.y;
        acc[i][2] = bw.z + x0 * wi0.z + x1 * wi1.z;
        acc[i][3] = bw.w + x0 * wi0.w + x1 * wi1.w;
    }
    tile_acc(acc, hin + (size_t)b0 * H, H, H, Whd, G4, wcol, a_sm, w_sm, tid, rg4, cg4);
    __syncthreads();
    store_gates(acc, gate_sm, rg4, cg4);
    __syncthreads();
    cell_update(gate_sm, tid, b0, u0, cd, hout,
                g_l0 + (size_t)t * B * E2 + dir * H, E2);
}

__global__ void __launch_bounds__(128) enc1_step(
    const float* __restrict__ Wih, const float* __restrict__ Whh,
    const float* __restrict__ bias, int s)
{
    __shared__ float a_sm[2 * 16 * 32], w_sm[2 * 16 * 64], gate_sm[32 * 64];
    int tid = threadIdx.x, dir = blockIdx.z;
    int t = dir ? (T - 1 - s) : s;
    int u0 = blockIdx.x * 16, b0 = blockIdx.y * 32;
    int cg4 = (tid & 15) * 4, rg4 = (tid >> 4) * 4;
    int wcol = (cg4 >> 4) * H + u0 + (cg4 & 15);

    const float* Wd  = Wih + (size_t)dir * E2 * G4;
    const float* Whd = Whh + (size_t)dir * H * G4;
    const float* bd  = bias + dir * G4;
    float* hin  = g_eh + (s & 1) * 2 * BH + dir * BH;
    float* hout = g_eh + ((s + 1) & 1) * 2 * BH + dir * BH;
    float* cd   = g_ec + dir * BH;

    float4 bw = *(const float4*)(bd + wcol);
    float acc[4][4];
#pragma unroll
    for (int i = 0; i < 4; ++i) {
        acc[i][0] = bw.x; acc[i][1] = bw.y; acc[i][2] = bw.z; acc[i][3] = bw.w;
    }
    tile_acc(acc, g_l0 + (size_t)t * B * E2 + (size_t)b0 * E2, E2, E2, Wd, G4, wcol,
             a_sm, w_sm, tid, rg4, cg4);
    tile_acc(acc, hin + (size_t)b0 * H, H, H, Whd, G4, wcol, a_sm, w_sm, tid, rg4, cg4);
    __syncthreads();
    store_gates(acc, gate_sm, rg4, cg4);
    __syncthreads();
    cell_update(gate_sm, tid, b0, u0, cd, hout,
                g_enc + (size_t)t * E2 + dir * H, (size_t)T * E2);
}

__global__ void __launch_bounds__(128) dec_step(
    const float* __restrict__ Wih, const float* __restrict__ Whh,
    const float* __restrict__ bias, int layer, int s)
{
    __shared__ float a_sm[2 * 16 * 32], w_sm[2 * 16 * 64], gate_sm[32 * 64];
    int tid = threadIdx.x;
    int u0 = blockIdx.x * 16, b0 = blockIdx.y * 32;
    int cg4 = (tid & 15) * 4, rg4 = (tid >> 4) * 4;
    int wcol = (cg4 >> 4) * H + u0 + (cg4 & 15);

    const float* Wd  = Wih + (size_t)layer * H * G4;
    const float* Whd = Whh + (size_t)layer * H * G4;
    const float* bd  = bias + layer * G4;
    const float* A1  = (layer == 0) ? g_din : (g_dh + ((s + 1) & 1) * 2 * BH);
    float* hin  = g_dh + (s & 1) * 2 * BH + layer * BH;
    float* hout = g_dh + ((s + 1) & 1) * 2 * BH + layer * BH;
    float* cd   = g_dc + layer * BH;

    float4 bw = *(const float4*)(bd + wcol);
    float acc[4][4];
#pragma unroll
    for (int i = 0; i < 4; ++i) {
        acc[i][0] = bw.x; acc[i][1] = bw.y; acc[i][2] = bw.z; acc[i][3] = bw.w;
    }
    tile_acc(acc, A1 + (size_t)b0 * H, H, H, Wd, G4, wcol, a_sm, w_sm, tid, rg4, cg4);
    tile_acc(acc, hin + (size_t)b0 * H, H, H, Whd, G4, wcol, a_sm, w_sm, tid, rg4, cg4);
    __syncthreads();
    store_gates(acc, gate_sm, rg4, cg4);
    __syncthreads();
    cell_update(gate_sm, tid, b0, u0, cd, hout, nullptr, 0);
}

__device__ __forceinline__ void gemm_core(
    const float* A1, int lda1, int K1, const float* W1,
    const float* A2, int lda2, int K2, const float* W2,
    int ldw, const float* bias, float* C, int ldc,
    float* a_sm, float* w_sm)
{
    int tid = threadIdx.x;
    int n0 = blockIdx.x * 64, b0 = blockIdx.y * 32;
    int cg4 = (tid & 15) * 4, rg4 = (tid >> 4) * 4;
    int wcol = n0 + cg4;
    float4 bw = *(const float4*)(bias + wcol);
    float acc[4][4];
#pragma unroll
    for (int i = 0; i < 4; ++i) {
        acc[i][0] = bw.x; acc[i][1] = bw.y; acc[i][2] = bw.z; acc[i][3] = bw.w;
    }
    tile_acc(acc, A1 + (size_t)b0 * lda1, lda1, K1, W1, ldw, wcol, a_sm, w_sm, tid, rg4, cg4);
    if (K2 > 0)
        tile_acc(acc, A2 + (size_t)b0 * lda2, lda2, K2, W2, ldw, wcol, a_sm, w_sm, tid, rg4, cg4);
#pragma unroll
    for (int i = 0; i < 4; ++i)
        *(float4*)(C + (size_t)(b0 + rg4 + i) * ldc + wcol) =
            make_float4(acc[i][0], acc[i][1], acc[i][2], acc[i][3]);
}

__global__ void __launch_bounds__(128) query_kernel(const float* __restrict__ Wq,
                                                    const float* __restrict__ bq, int s)
{
    __shared__ float a_sm[2 * 16 * 32], w_sm[2 * 16 * 64];
    const float* h1 = g_dh + ((s + 1) & 1) * 2 * BH + BH;
    gemm_core(h1, H, H, Wq, nullptr, 0, 0, nullptr, E2, bq, g_q, E2, a_sm, w_sm);
}

__global__ void __launch_bounds__(128) comb_kernel(const float* __restrict__ Wc,
                                                   const float* __restrict__ bc, int s)
{
    __shared__ float a_sm[2 * 16 * 32], w_sm[2 * 16 * 64];
    const float* h1 = g_dh + ((s + 1) & 1) * 2 * BH + BH;
    gemm_core(h1, H, H, Wc, g_cx, E2, E2, Wc + (size_t)H * H, H, bc, g_cb, H, a_sm, w_sm);
}

__global__ void __launch_bounds__(128) logits_kernel(const float* __restrict__ Wf,
                                                     const float* __restrict__ bf,
                                                     float* __restrict__ out, int s)
{
    __shared__ float a_sm[2 * 16 * 32], w_sm[2 * 16 * 64];
    gemm_core(g_cb, H, H, Wf, nullptr, 0, 0, nullptr, V, bf,
              out + (size_t)s * V, LW * V, a_sm, w_sm);
}

__global__ void __launch_bounds__(256) attn_kernel(float* __restrict__ out, int step)
{
    __shared__ float qs[E2];
    __shared__ float sc[T];
    __shared__ float red[8];
    int b = blockIdx.x, tid = threadIdx.x;
    const float* eb = g_enc + (size_t)b * T * E2;
    for (int j = tid; j < E2; j += 256) qs[j] = g_q[b * E2 + j];
    __syncthreads();
    int warp = tid >> 5, lane = tid & 31;
    for (int t = warp; t < T; t += 8) {
        const float* er = eb + (size_t)t * E2;
        float acc = 0.f;
#pragma unroll 8
        for (int j = lane; j < E2; j += 32) acc += er[j] * qs[j];
#pragma unroll
        for (int o = 16; o; o >>= 1) acc += __shfl_xor_sync(0xffffffffu, acc, o);
        if (lane == 0) sc[t] = acc;
    }
    __syncthreads();
    float v = sc[tid];
    float m = v;
#pragma unroll
    for (int o = 16; o; o >>= 1) m = fmaxf(m, __shfl_xor_sync(0xffffffffu, m, o));
    if (lane == 0) red[warp] = m;
    __syncthreads();
    float bm = red[0];
#pragma unroll
    for (int w = 1; w < 8; ++w) bm = fmaxf(bm, red[w]);
    float e = expf(v - bm);
    float ssum = e;
#pragma unroll
    for (int o = 16; o; o >>= 1) ssum += __shfl_xor_sync(0xffffffffu, ssum, o);
    __syncthreads();
    if (lane == 0) red[warp] = ssum;
    __syncthreads();
    float tot = 0.f;
#pragma unroll
    for (int w = 0; w < 8; ++w) tot += red[w];
    float p = e / tot;
    sc[tid] = p;
    out[OUT_ATT + (size_t)b * T * LW + (size_t)tid * LW + step] = p;
    __syncthreads();
    float a0 = 0.f, a1 = 0.f, a2 = 0.f, a3 = 0.f;
    for (int t = 0; t < T; ++t) {
        float pt = sc[t];
        const float* er = eb + (size_t)t * E2;
        a0 = fmaf(pt, er[tid], a0);
        a1 = fmaf(pt, er[tid + 256], a1);
        a2 = fmaf(pt, er[tid + 512], a2);
        a3 = fmaf(pt, er[tid + 768], a3);
    }
    g_cx[b * E2 + tid]       = a0;
    g_cx[b * E2 + tid + 256] = a1;
    g_cx[b * E2 + tid + 512] = a2;
    g_cx[b * E2 + tid + 768] = a3;
}

__global__ void argmax_kernel(const float* __restrict__ out, int step)
{
    int b = blockIdx.x, tid = threadIdx.x;   // 128 threads = V
    float v = out[(size_t)b * LW * V + (size_t)step * V + tid];
    int idx = tid;
#pragma unroll
    for (int o = 16; o; o >>= 1) {
        float ov = __shfl_xor_sync(0xffffffffu, v, o);
        int oi = __shfl_xor_sync(0xffffffffu, idx, o);
        if (ov > v || (ov == v && oi < idx)) { v = ov; idx = oi; }
    }
    __shared__ float sv[4];
    __shared__ int si[4];
    if ((tid & 31) == 0) { sv[tid >> 5] = v; si[tid >> 5] = idx; }
    __syncthreads();
    if (tid == 0) {
#pragma unroll
        for (int w = 1; w < 4; ++w)
            if (sv[w] > v || (sv[w] == v && si[w] < idx)) { v = sv[w]; idx = si[w]; }
        g_tok[b] = idx;
    }
}

__global__ void gather_emb(const float* __restrict__ emb)
{
    g_din[blockIdx.x * H + threadIdx.x] = emb[(size_t)g_tok[blockIdx.x] * H + threadIdx.x];
}

__global__ void init_tok() { g_tok[threadIdx.x] = 1; }   // SOS = 1

__global__ void zero_enc()
{
    int i = blockIdx.x * blockDim.x + threadIdx.x;
    if (i < 4 * BH) g_eh[i] = 0.f;
    if (i < 2 * BH) g_ec[i] = 0.f;
}

__global__ void sum_states(int l)
{
    int i = blockIdx.x * blockDim.x + threadIdx.x;
    if (i < BH) {
        g_dh[l * BH + i] = g_eh[i] + g_eh[BH + i];   // phase0 holds finals after T steps
        g_dc[l * BH + i] = g_ec[i] + g_ec[BH + i];
    }
}

__global__ void final_copy(float* __restrict__ out)
{
    int i = blockIdx.x * blockDim.x + threadIdx.x;
    if (i < NL * BH) {
        out[OUT_HF + i] = g_dh[i];   // phase 0 after 32 decoder steps
        out[OUT_CF + i] = g_dc[i];
    }
}

extern "C" void kernel_launch(void* const* d_in, const int* in_sizes, int n_in,
                              void* d_out, int out_size)
{
    const float* x     = (const float*)d_in[0];
    const float* e0Wih = (const float*)d_in[1];
    const float* e0Whh = (const float*)d_in[2];
    const float* e0b   = (const float*)d_in[3];
    const float* e1Wih = (const float*)d_in[4];
    const float* e1Whh = (const float*)d_in[5];
    const float* e1b   = (const float*)d_in[6];
    const float* dWih  = (const float*)d_in[7];
    const float* dWhh  = (const float*)d_in[8];
    const float* db    = (const float*)d_in[9];
    const float* emb   = (const float*)d_in[10];
    const float* Wq    = (const float*)d_in[11];
    const float* bq    = (const float*)d_in[12];
    const float* Wc    = (const float*)d_in[13];
    const float* bc    = (const float*)d_in[14];
    const float* Wf    = (const float*)d_in[15];
    const float* bf    = (const float*)d_in[16];
    float* out = (float*)d_out;

    dim3 gL(32, 4, 2), gD(32, 4, 1);

    zero_enc<<<(4 * BH + 255) / 256, 256>>>();
    for (int s = 0; s < T; ++s)
        enc0_step<<<gL, 128>>>(x, e0Wih, e0Whh, e0b, s);
    sum_states<<<256, 256>>>(0);

    zero_enc<<<(4 * BH + 255) / 256, 256>>>();
    for (int s = 0; s < T; ++s)
        enc1_step<<<gL, 128>>>(e1Wih, e1Whh, e1b, s);
    sum_states<<<256, 256>>>(1);

    init_tok<<<1, B>>>();
    for (int s = 0; s < LW; ++s) {
        gather_emb<<<B, H>>>(emb);
        dec_step<<<gD, 128>>>(dWih, dWhh, db, 0, s);
        dec_step<<<gD, 128>>>(dWih, dWhh, db, 1, s);
        query_kernel<<<dim3(16, 4), 128>>>(Wq, bq, s);
        attn_kernel<<<B, 256>>>(out, s);
        comb_kernel<<<dim3(8, 4), 128>>>(Wc, bc, s);
        logits_kernel<<<dim3(2, 4), 128>>>(Wf, bf, out, s);
        argmax_kernel<<<B, 128>>>(out, s);
    }
    final_copy<<<512, 256>>>(out);
}